// round 2
// baseline (speedup 1.0000x reference)
#include <cuda_runtime.h>

// Problem constants
#define BB 8
#define DD 1024
#define TT 2048
#define KK 8192          // codebook size
#define CDIM 8           // codebook dim
#define NTOK (BB*TT)     // 16384 tokens
#define NPAIR (KK/2)     // 4096 code pairs
#define CHUNK_PAIRS 512
#define NCHUNK (NPAIR/CHUNK_PAIRS)   // 8 chunks

typedef unsigned long long ull;

// ---------------- scratch (static device globals; no runtime allocation) ----
__device__ float  g_enc[NTOK*CDIM];                    // normalized encodings
__device__ int    g_idx[NTOK];                         // argmax indices
__device__ __align__(16) float2 g_cbpack[NPAIR*CDIM];  // packed normalized codebook
__device__ __align__(16) float2 g_cninit[NPAIR];       // {-cn2_even/2, -cn2_odd/2}
__device__ float  g_wT[DD*CDIM];                       // w_in transposed [d][o]

// ---------------- f32x2 helpers (sm_100+/sm_103a packed fp32) ---------------
__device__ __forceinline__ ull pk2(float x, float y) {
    ull r; asm("mov.b64 %0, {%1,%2};" : "=l"(r) : "f"(x), "f"(y)); return r;
}
__device__ __forceinline__ void upk2(ull v, float& x, float& y) {
    asm("mov.b64 {%0,%1}, %2;" : "=f"(x), "=f"(y) : "l"(v));
}
__device__ __forceinline__ ull f2fma(ull a, ull b, ull c) {
    ull d; asm("fma.rn.f32x2 %0, %1, %2, %3;" : "=l"(d) : "l"(a), "l"(b), "l"(c));
    return d;
}

// ============================================================================
// K0: prep — normalize codebook, pack pairs for f32x2 search, transpose w_in,
//     zero the loss outputs.
// grid 16 x 256 = 4096 threads (one per code pair)
// ============================================================================
__global__ __launch_bounds__(256) void k0_prep(
    const float* __restrict__ w_in, const float* __restrict__ codebook,
    float* __restrict__ d_out, long long offLoss, int writeExtras)
{
    int g = blockIdx.x * blockDim.x + threadIdx.x;   // 0..4095

    // w_in transpose: g_wT[d*8+o] = w_in[o*DD + d]
    for (int x = g; x < DD*CDIM; x += 4096) {
        int d = x >> 3, o = x & 7;
        g_wT[x] = w_in[o*DD + d];
    }

    if (writeExtras && g < 16) d_out[offLoss + g] = 0.0f;   // commit+codebook loss

    if (g < NPAIR) {
        int p = g;
        float a[8], b[8], an[8], bn[8];
        float sa = 0.f, sb = 0.f;
        #pragma unroll
        for (int k = 0; k < 8; k++) { a[k] = codebook[(2*p)*CDIM + k];   sa = fmaf(a[k], a[k], sa); }
        #pragma unroll
        for (int k = 0; k < 8; k++) { b[k] = codebook[(2*p+1)*CDIM + k]; sb = fmaf(b[k], b[k], sb); }
        float da = fmaxf(sqrtf(sa), 1e-12f);
        float db = fmaxf(sqrtf(sb), 1e-12f);
        float cn2a = 0.f, cn2b = 0.f;
        #pragma unroll
        for (int k = 0; k < 8; k++) {
            an[k] = a[k] / da; cn2a = fmaf(an[k], an[k], cn2a);
            bn[k] = b[k] / db; cn2b = fmaf(bn[k], bn[k], cn2b);
        }
        // packed layout matching K2's smem access pattern
        int c = p / CHUNK_PAIRS, r = p % CHUNK_PAIRS;
        int i = r >> 3, tx = r & 7;
        float2* dst = g_cbpack + c * (CHUNK_PAIRS * CDIM);
        #pragma unroll
        for (int k = 0; k < 8; k++) {
            int k2 = k >> 1, klo = k & 1;
            dst[((((i*4 + k2)*8) + tx) << 1) + klo] = make_float2(an[k], bn[k]);
        }
        g_cninit[p] = make_float2(-0.5f * cn2a, -0.5f * cn2b);
    }
}

// ============================================================================
// K1: z_e = w_in @ z + b_in; write z_e output region; store normalized enc.
// grid = 256 CTAs (b in [0,8) x 32 t-tiles of 64), 256 threads:
//   tl = tid&63 -> token within tile; ds = tid>>6 -> d-slice of 256
// ============================================================================
__global__ __launch_bounds__(256) void k1_encode(
    const float* __restrict__ z, const float* __restrict__ b_in,
    float* __restrict__ d_out, long long offZe, int writeExtras)
{
    __shared__ float s_w[DD*CDIM];     // 32KB, [d][o]
    __shared__ float s_red[256*8];     // 8KB partials

    int tid = threadIdx.x;
    for (int x = tid; x < DD*CDIM; x += 256) s_w[x] = g_wT[x];
    __syncthreads();

    int b = blockIdx.x >> 5;
    int tbase = (blockIdx.x & 31) * 64;
    int tl = tid & 63, ds = tid >> 6;
    int t = tbase + tl;

    const float* zp = z + (long long)b * DD * TT + t;
    float acc[8] = {0.f,0.f,0.f,0.f,0.f,0.f,0.f,0.f};
    int d0 = ds * 256;
    #pragma unroll 8
    for (int d = d0; d < d0 + 256; d++) {
        float zv = zp[(long long)d * TT];
        float4 w0 = *(const float4*)(s_w + d*8);
        float4 w1 = *(const float4*)(s_w + d*8 + 4);
        acc[0] = fmaf(zv, w0.x, acc[0]);
        acc[1] = fmaf(zv, w0.y, acc[1]);
        acc[2] = fmaf(zv, w0.z, acc[2]);
        acc[3] = fmaf(zv, w0.w, acc[3]);
        acc[4] = fmaf(zv, w1.x, acc[4]);
        acc[5] = fmaf(zv, w1.y, acc[5]);
        acc[6] = fmaf(zv, w1.z, acc[6]);
        acc[7] = fmaf(zv, w1.w, acc[7]);
    }
    #pragma unroll
    for (int o = 0; o < 8; o++) s_red[tid*8 + o] = acc[o];
    __syncthreads();

    if (tid < 64) {
        float e[8];
        #pragma unroll
        for (int o = 0; o < 8; o++) {
            e[o] = ((s_red[(tid)*8 + o]       + s_red[(64+tid)*8 + o])
                 + (s_red[(128+tid)*8 + o] + s_red[(192+tid)*8 + o])) + b_in[o];
        }
        float ss = 0.f;
        #pragma unroll
        for (int o = 0; o < 8; o++) ss = fmaf(e[o], e[o], ss);
        float den = fmaxf(sqrtf(ss), 1e-12f);
        int tt = tbase + tid;
        int tok = b * TT + tt;
        #pragma unroll
        for (int o = 0; o < 8; o++) {
            if (writeExtras)
                d_out[offZe + ((long long)b*CDIM + o)*TT + tt] = e[o];
            g_enc[tok*CDIM + o] = e[o] / den;
        }
    }
}

// ============================================================================
// K2: codebook argmax search. score = dot(enc_n, cb_n) - cn2/2, first-max wins.
// grid = 128 CTAs x 128 tokens, 256 threads:
//   tx = tid&7 -> code slice (interleaved pairs), ty = tid>>3 -> 4 tokens
// f32x2: each FFMA2 advances one k for TWO codes (even/odd of a pair).
// ============================================================================
__global__ __launch_bounds__(256, 1) void k2_search(
    float* __restrict__ d_out, long long offIdx, int writeExtras)
{
    __shared__ __align__(16) float2 s_cb[CHUNK_PAIRS*CDIM];  // 32KB
    __shared__ __align__(16) float2 s_cn[CHUNK_PAIRS];       // 4KB

    int tid = threadIdx.x;
    int tx = tid & 7, ty = tid >> 3;
    int tokbase = blockIdx.x * 128 + ty * 4;

    // enc packed {e_k, e_k} for 4 tokens
    ull ee[4][8];
    #pragma unroll
    for (int j = 0; j < 4; j++) {
        #pragma unroll
        for (int k = 0; k < 8; k++) {
            float e = g_enc[(tokbase + j)*CDIM + k];
            ee[j][k] = pk2(e, e);
        }
    }
    float best[4];
    int   bidx[4];
    #pragma unroll
    for (int j = 0; j < 4; j++) { best[j] = -3.402823466e38f; bidx[j] = 0; }

    for (int c = 0; c < NCHUNK; c++) {
        __syncthreads();
        {   // cooperative chunk load (coalesced uint4 copies)
            const uint4* src = (const uint4*)(g_cbpack + (long long)c * CHUNK_PAIRS * CDIM);
            uint4* dst = (uint4*)s_cb;
            #pragma unroll
            for (int u = tid; u < CHUNK_PAIRS*CDIM/2; u += 256) dst[u] = src[u];
            const uint4* srcn = (const uint4*)(g_cninit + (long long)c * CHUNK_PAIRS);
            ((uint4*)s_cn)[tid] = srcn[tid];
        }
        __syncthreads();

        #pragma unroll 2
        for (int i = 0; i < CHUNK_PAIRS/8; i++) {   // 64 iters
            ull cd[8];
            #pragma unroll
            for (int k2 = 0; k2 < 4; k2++) {
                ulonglong2 v = *(const ulonglong2*)(s_cb + ((((i*4 + k2)*8) + tx) << 1));
                cd[2*k2]     = v.x;
                cd[2*k2 + 1] = v.y;
            }
            ull cn = *(const ull*)(s_cn + (i*8 + tx));
            int pb = ((c * CHUNK_PAIRS + i*8 + tx) << 1);   // even code index
            #pragma unroll
            for (int j = 0; j < 4; j++) {
                ull a = cn;
                #pragma unroll
                for (int k = 0; k < 8; k++) a = f2fma(ee[j][k], cd[k], a);
                float lo, hi; upk2(a, lo, hi);
                if (lo > best[j]) { best[j] = lo; bidx[j] = pb; }
                if (hi > best[j]) { best[j] = hi; bidx[j] = pb + 1; }
            }
        }
    }

    // reduce across the 8 tx lanes (same warp); ties -> smaller index
    #pragma unroll
    for (int j = 0; j < 4; j++) {
        float bv = best[j]; int bi = bidx[j];
        #pragma unroll
        for (int m = 1; m < 8; m <<= 1) {
            float ov = __shfl_xor_sync(0xFFFFFFFFu, bv, m);
            int   oi = __shfl_xor_sync(0xFFFFFFFFu, bi, m);
            if (ov > bv || (ov == bv && oi < bi)) { bv = ov; bi = oi; }
        }
        if (tx == 0) {
            int tok = tokbase + j;
            g_idx[tok] = bi;
            if (writeExtras) d_out[offIdx + tok] = (float)bi;
        }
    }
}

// ============================================================================
// K3: out = w_out @ codebook[idx] + b_out  (z_q_st == z_q in forward)
// grid = 256 CTAs (b x 32 t-tiles of 64), 256 threads:
//   tl = tid&63 -> token, os = tid>>6 -> o-slice of 256
// ============================================================================
__global__ __launch_bounds__(256) void k3_decode(
    const float* __restrict__ w_out, const float* __restrict__ b_out,
    const float* __restrict__ codebook, float* __restrict__ out)
{
    __shared__ float s_w[DD*CDIM];   // 32KB, [o][k] (== w_out layout)
    __shared__ float s_b[DD];        // 4KB

    int tid = threadIdx.x;
    for (int x = tid; x < DD*CDIM; x += 256) s_w[x] = w_out[x];
    for (int x = tid; x < DD;      x += 256) s_b[x] = b_out[x];
    __syncthreads();

    int b = blockIdx.x >> 5;
    int tbase = (blockIdx.x & 31) * 64;
    int tl = tid & 63, os = tid >> 6;
    int t = tbase + tl;
    int tok = b * TT + t;

    int idx = g_idx[tok];
    const float* cp = codebook + (long long)idx * CDIM;
    float4 ca = *(const float4*)cp;
    float4 cb = *(const float4*)(cp + 4);

    long long obase = (long long)b * DD * TT + t;
    int o0 = os * 256;
    #pragma unroll 4
    for (int o = o0; o < o0 + 256; o++) {
        float4 w0 = *(const float4*)(s_w + o*8);
        float4 w1 = *(const float4*)(s_w + o*8 + 4);
        float acc = s_b[o];
        acc = fmaf(ca.x, w0.x, acc);
        acc = fmaf(ca.y, w0.y, acc);
        acc = fmaf(ca.z, w0.z, acc);
        acc = fmaf(ca.w, w0.w, acc);
        acc = fmaf(cb.x, w1.x, acc);
        acc = fmaf(cb.y, w1.y, acc);
        acc = fmaf(cb.z, w1.z, acc);
        acc = fmaf(cb.w, w1.w, acc);
        out[obase + (long long)o * TT] = acc;
    }
}

// ============================================================================
extern "C" void kernel_launch(void* const* d_in, const int* in_sizes, int n_in,
                              void* d_out, int out_size)
{
    const float* z        = (const float*)d_in[0];
    const float* w_in     = (const float*)d_in[1];
    const float* b_in     = (const float*)d_in[2];
    const float* w_out    = (const float*)d_in[3];
    const float* b_out    = (const float*)d_in[4];
    const float* codebook = (const float*)d_in[5];
    float* out = (float*)d_out;

    long long nOut   = (long long)BB * DD * TT;       // 16,777,216
    long long offLoss = nOut;                          // 16 loss zeros
    long long offIdx  = nOut + 16;                     // 16,384 indices
    long long offZe   = nOut + 16 + NTOK;              // 131,072 z_e
    long long total   = offZe + (long long)NTOK * CDIM;
    int writeExtras = ((long long)out_size >= total) ? 1 : 0;

    k0_prep  <<<16,  256>>>(w_in, codebook, out, offLoss, writeExtras);
    k1_encode<<<256, 256>>>(z, b_in, out, offZe, writeExtras);
    k2_search<<<128, 256>>>(out, offIdx, writeExtras);
    k3_decode<<<256, 256>>>(w_out, b_out, codebook, out);
}